// round 17
// baseline (speedup 1.0000x reference)
#include <cuda_runtime.h>
#include <cstdint>

// LIF spike scan. x: [64, 8192, 100] fp32 (T contiguous) -> spikes (same shape).
//   mem = mem*TAU + x_t - w ; spike = (mem > THRESH)
//   w = BETA*w + (1-BETA)*(A*mem + B*spike) ; mem -= spike*THRESH
//
// R17 = R10 economics (8192 CTAs, 25.6KB/CTA, 8 CTAs/SM, TMA bulk, evict_first,
// conflict-free float4 scan) with INTRA-CTA WARP DECOUPLING: each of the two
// warps owns an independent 32-row half-tile with its own mbarrier, its own
// TMA load and its own TMA store. No __syncthreads at all -> 16 independent
// phase machines per SM at 8-CTA launch overhead; each half computes as soon
// as ITS 12.8KB lands and stores as soon as ITS scan finishes.

#define TAU    0.5f
#define THRESH 0.5f
#define BETA   0.9f
#define C_MS   0.05f   // (1-BETA)*A == (1-BETA)*B

constexpr int T_LEN       = 100;
constexpr int ROWS        = 64;                   // threads/CTA (2 warps)
constexpr int TILE_FLOATS = ROWS * T_LEN;         // 6400
constexpr int HALF_ROWS   = 32;                   // rows per warp
constexpr int HALF_FLOATS = HALF_ROWS * T_LEN;    // 3200
constexpr int HALF_BYTES  = HALF_FLOATS * 4;      // 12800
constexpr int DATA_OFF    = 32;                   // two mbarrier slots
constexpr int SMEM_BYTES  = DATA_OFF + 2 * HALF_BYTES;   // 25,632 -> 8 CTAs/SM

__device__ __forceinline__ void lif_step(float xt, float& mem, float& w, float& sp) {
    float m2 = fmaf(mem, TAU, xt) - w;
    bool fire = (m2 > THRESH);
    sp  = fire ? 1.0f : 0.0f;
    w   = fmaf(BETA, w, fmaf(C_MS, m2, C_MS * sp));
    mem = fire ? (m2 - THRESH) : m2;     // FSETP -> FSEL, short dep chain
}

__global__ __launch_bounds__(ROWS, 8) void lif_kernel(const float* __restrict__ x,
                                                      float* __restrict__ out) {
    extern __shared__ float smem[];
    const int tid  = threadIdx.x;
    const int wid  = tid >> 5;        // 0 or 1: which half-tile this warp owns
    const int lane = tid & 31;

    uint32_t sb;
    asm("{ .reg .u64 t; cvta.to.shared.u64 t, %1; cvt.u32.u64 %0, t; }"
        : "=r"(sb) : "l"(smem));
    const uint32_t mbar = sb + (uint32_t)wid * 16u;
    const uint32_t dsh  = sb + DATA_OFF + (uint32_t)wid * HALF_BYTES;
    float* buf = smem + DATA_OFF / 4 + wid * HALF_FLOATS;

    const size_t half_base = (size_t)blockIdx.x * TILE_FLOATS
                           + (size_t)wid * HALF_FLOATS;
    const float* __restrict__ xin  = x   + half_base;
    float* __restrict__       xout = out + half_base;

    // Streaming L2 policy: evict_first for touch-once data.
    uint64_t pol;
    asm volatile("createpolicy.fractional.L2::evict_first.b64 %0, 1.0;" : "=l"(pol));

    // Per-warp: init own mbarrier and kick own half-tile load.
    if (lane == 0) {
        asm volatile("mbarrier.init.shared.b64 [%0], 1;" :: "r"(mbar) : "memory");
        asm volatile("mbarrier.arrive.expect_tx.shared.b64 _, [%0], %1;"
                     :: "r"(mbar), "r"((uint32_t)HALF_BYTES) : "memory");
        asm volatile("cp.async.bulk.shared::cta.global.mbarrier::complete_tx::bytes"
                     ".L2::cache_hint [%0], [%1], %2, [%3], %4;"
                     :: "r"(dsh), "l"(xin), "r"((uint32_t)HALF_BYTES),
                        "r"(mbar), "l"(pol) : "memory");
    }
    __syncwarp();   // warp sees its initialized mbarrier

    // Wait for this warp's half (parity 0), acquire for the LDS reads.
    {
        uint32_t done;
        asm volatile(
            "{\n\t.reg .pred p;\n\t"
            "mbarrier.try_wait.parity.acquire.cta.shared::cta.b64 p, [%1], 0;\n\t"
            "selp.b32 %0, 1, 0, p;\n\t}"
            : "=r"(done) : "r"(mbar) : "memory");
        if (!done) {
            asm volatile(
                "{\n\t.reg .pred P1;\n\t"
                "WL_%=:\n\t"
                "mbarrier.try_wait.parity.acquire.cta.shared::cta.b64 P1, [%0], 0, 0x989680;\n\t"
                "@P1 bra.uni WD_%=;\n\t"
                "bra.uni WL_%=;\n\t"
                "WD_%=:\n\t}"
                :: "r"(mbar) : "memory");
        }
    }

    // Scan: one lane per row; float4 smem access is bank-conflict-free
    // (100 % 32 == 4: each quarter-warp phase covers all 32 banks once).
    {
        float4* srow = reinterpret_cast<float4*>(buf + lane * T_LEN);
        float mem = 0.0f, w = 0.0f;
        #pragma unroll
        for (int j = 0; j < T_LEN / 4; j++) {
            float4 v = srow[j];
            float4 sp;
            lif_step(v.x, mem, w, sp.x);
            lif_step(v.y, mem, w, sp.y);
            lif_step(v.z, mem, w, sp.z);
            lif_step(v.w, mem, w, sp.w);
            srow[j] = sp;
        }
    }
    __syncwarp();

    // Per-warp bulk store of its half. Wait only for the smem-READ phase
    // before exit; GMEM writes drain under the kernel-end fence.
    if (lane == 0) {
        asm volatile("fence.proxy.async.shared::cta;" ::: "memory");
        asm volatile("cp.async.bulk.global.shared::cta.bulk_group"
                     ".L2::cache_hint [%0], [%1], %2, %3;"
                     :: "l"(xout), "r"(dsh), "r"((uint32_t)HALF_BYTES),
                        "l"(pol) : "memory");
        asm volatile("cp.async.bulk.commit_group;" ::: "memory");
        asm volatile("cp.async.bulk.wait_group.read 0;" ::: "memory");
    }
}

extern "C" void kernel_launch(void* const* d_in, const int* in_sizes, int n_in,
                              void* d_out, int out_size) {
    const float* x = (const float*)d_in[0];
    float* out = (float*)d_out;
    int grid = in_sizes[0] / TILE_FLOATS;      // 8192

    cudaFuncSetAttribute(lif_kernel, cudaFuncAttributeMaxDynamicSharedMemorySize,
                         SMEM_BYTES);
    lif_kernel<<<grid, ROWS, SMEM_BYTES>>>(x, out);
}